// round 5
// baseline (speedup 1.0000x reference)
#include <cuda_runtime.h>

// RNN_43920335569315: vanilla tanh RNN. B=8192, T=512, I=H=7, O=1.
//   h_t = tanh(x_t W_ih^T + b_ih + b_hh + h_{t-1} W_hh^T);  out = h.W_fc + b_fc
// d_in = {x, W_ih, W_hh, b_ih, b_hh, W_fc, b_fc};  d_out = concat(out[B,T], h_T[1,B,H]).
//
// Round-5: same 4-lanes-per-element dataflow as R4, but:
//  * 256-thread blocks, grid=128  ->  one block per SM, UNIFORM 2 warps/SMSP
//    (R4's 256x128 grid left 40 SMs with 1 warp/SMSP; they set the wall clock).
//  * out-projection as per-lane partial + once-per-4-steps butterfly reduce.
//  * bias packs hoisted out of the loop.

#define RNN_B 8192
#define RNN_T 512
#define RNN_H 7

typedef unsigned long long u64;

__device__ __forceinline__ u64 pk2(float lo, float hi) {
    u64 r; asm("mov.b64 %0, {%1, %2};" : "=l"(r) : "f"(lo), "f"(hi)); return r;
}
__device__ __forceinline__ void upk2(u64 v, float& lo, float& hi) {
    asm("mov.b64 {%0, %1}, %2;" : "=f"(lo), "=f"(hi) : "l"(v));
}
__device__ __forceinline__ u64 fma2(u64 a, u64 b, u64 c) {
    u64 d; asm("fma.rn.f32x2 %0, %1, %2, %3;" : "=l"(d) : "l"(a), "l"(b), "l"(c)); return d;
}
__device__ __forceinline__ u64 mul2(u64 a, u64 b) {
    u64 d; asm("mul.rn.f32x2 %0, %1, %2;" : "=l"(d) : "l"(a), "l"(b)); return d;
}
__device__ __forceinline__ u64 add2(u64 a, u64 b) {
    u64 d; asm("add.rn.f32x2 %0, %1, %2;" : "=l"(d) : "l"(a), "l"(b)); return d;
}
__device__ __forceinline__ float tanh_ap(float x) {
    float y; asm("tanh.approx.f32 %0, %1;" : "=f"(y) : "f"(x)); return y;
}

__global__ void __launch_bounds__(256, 1) rnn_fused_kernel(
    const float* __restrict__ x,
    const float* __restrict__ W_ih,
    const float* __restrict__ W_hh,
    const float* __restrict__ b_ih,
    const float* __restrict__ b_hh,
    const float* __restrict__ W_fc,
    const float* __restrict__ b_fc,
    float* __restrict__ out,
    float* __restrict__ hidden)
{
    const int tid = blockIdx.x * 256 + threadIdx.x;
    const int sub = tid & 3;          // quarter of the 8-padded H this lane owns
    const int b   = tid >> 2;         // batch element (4 consecutive lanes)

    const int r0 = 2 * sub;           // my rows: r0, r0+1 (row 7 is zero pad)
    const int r1 = r0 + 1;

    // ---- weights ----
    u64 wih_o[2][4];                  // x-proj pairs, natural i-pair order
    u64 whh_o[2][4];                  // rec pairs in xor order j (pack from lane sub^j)
    float bias2[2];
#pragma unroll
    for (int m = 0; m < 2; ++m) {
        const int r = r0 + m;
        const bool ok = (r < RNN_H);
#pragma unroll
        for (int p = 0; p < 4; ++p) {
            const int i0 = 2 * p, i1 = 2 * p + 1;
            wih_o[m][p] = pk2((ok && i0 < RNN_H) ? __ldg(&W_ih[r * RNN_H + i0]) : 0.0f,
                              (ok && i1 < RNN_H) ? __ldg(&W_ih[r * RNN_H + i1]) : 0.0f);
            const int ps = sub ^ p;
            const int k0 = 2 * ps, k1 = 2 * ps + 1;
            whh_o[m][p] = pk2((ok && k0 < RNN_H) ? __ldg(&W_hh[r * RNN_H + k0]) : 0.0f,
                              (ok && k1 < RNN_H) ? __ldg(&W_hh[r * RNN_H + k1]) : 0.0f);
        }
        bias2[m] = ok ? (__ldg(&b_ih[r]) + __ldg(&b_hh[r])) : 0.0f;
    }
    const u64 biasp0 = pk2(bias2[0], 0.0f);
    const u64 biasp1 = pk2(bias2[1], 0.0f);

    // fc weights: only my own pair (partials reduced across lanes later)
    const u64 wfc_own = pk2(__ldg(&W_fc[r0]),
                            (r1 < RNN_H) ? __ldg(&W_fc[r1]) : 0.0f);
    const float bo = __ldg(&b_fc[0]);

    const float4* __restrict__ xq =
        reinterpret_cast<const float4*>(x + (size_t)b * RNN_T * RNN_H);
    float* __restrict__ outp = out + (size_t)b * RNN_T;

    u64 hP = 0, hX1 = 0, hX2 = 0, hX3 = 0;
    float t0 = 0.f, t1 = 0.f;

    float bufA[28], bufB[28];
#pragma unroll
    for (int q = 0; q < 7; ++q)
        reinterpret_cast<float4*>(bufA)[q] = __ldg(&xq[q]);

#define LOAD_GROUP(BUF, G) do {                                              \
        _Pragma("unroll")                                                    \
        for (int q = 0; q < 7; ++q)                                          \
            reinterpret_cast<float4*>(BUF)[q] = __ldg(&xq[(size_t)(G) * 7 + q]); \
    } while (0)

#define PROCESS_GROUP(BUF, G) do {                                          \
        /* base partials for all 4 steps: independent stall filler */       \
        u64 basep[4][2];                                                    \
        _Pragma("unroll")                                                   \
        for (int st = 0; st < 4; ++st) {                                    \
            const float* xv = (BUF) + st * RNN_H;                           \
            const u64 xp0 = pk2(xv[0], xv[1]);                              \
            const u64 xp1 = pk2(xv[2], xv[3]);                              \
            const u64 xp2 = pk2(xv[4], xv[5]);                              \
            const u64 xp3 = pk2(xv[6], 0.0f);                               \
            u64 a0 = fma2(wih_o[0][0], xp0, biasp0);                        \
            u64 a1 = fma2(wih_o[1][0], xp0, biasp1);                        \
            a0 = fma2(wih_o[0][1], xp1, a0);                                \
            a1 = fma2(wih_o[1][1], xp1, a1);                                \
            a0 = fma2(wih_o[0][2], xp2, a0);                                \
            a1 = fma2(wih_o[1][2], xp2, a1);                                \
            a0 = fma2(wih_o[0][3], xp3, a0);                                \
            a1 = fma2(wih_o[1][3], xp3, a1);                                \
            basep[st][0] = a0;                                              \
            basep[st][1] = a1;                                              \
        }                                                                   \
        float part[4];                                                      \
        _Pragma("unroll")                                                   \
        for (int st = 0; st < 4; ++st) {                                    \
            u64 a0 = fma2(whh_o[0][0], hP, basep[st][0]);                   \
            u64 a1 = fma2(whh_o[1][0], hP, basep[st][1]);                   \
            a0 = fma2(whh_o[0][1], hX1, a0);                                \
            a1 = fma2(whh_o[1][1], hX1, a1);                                \
            a0 = fma2(whh_o[0][2], hX2, a0);                                \
            a1 = fma2(whh_o[1][2], hX2, a1);                                \
            a0 = fma2(whh_o[0][3], hX3, a0);                                \
            a1 = fma2(whh_o[1][3], hX3, a1);                                \
            float l0, u0, l1, u1;                                           \
            upk2(a0, l0, u0); upk2(a1, l1, u1);                             \
            t0 = tanh_ap(l0 + u0);                                          \
            t1 = tanh_ap(l1 + u1);                                          \
            hP = pk2(t0, t1);                                               \
            hX1 = __shfl_xor_sync(0xFFFFFFFFu, hP, 1);                      \
            hX2 = __shfl_xor_sync(0xFFFFFFFFu, hP, 2);                      \
            hX3 = __shfl_xor_sync(0xFFFFFFFFu, hP, 3);                      \
            /* per-lane out partial: wfc_own . hP (folded) */               \
            float pl, pu;                                                   \
            upk2(mul2(wfc_own, hP), pl, pu);                                \
            part[st] = pl + pu;                                             \
        }                                                                   \
        /* butterfly-reduce out partials across the 4 lanes of the group */ \
        u64 p01 = pk2(part[0], part[1]);                                    \
        u64 p23 = pk2(part[2], part[3]);                                    \
        p01 = add2(p01, __shfl_xor_sync(0xFFFFFFFFu, p01, 1));              \
        p23 = add2(p23, __shfl_xor_sync(0xFFFFFFFFu, p23, 1));              \
        p01 = add2(p01, __shfl_xor_sync(0xFFFFFFFFu, p01, 2));              \
        p23 = add2(p23, __shfl_xor_sync(0xFFFFFFFFu, p23, 2));              \
        if (sub == 0) {                                                     \
            float4 ov;                                                      \
            float a, c;                                                     \
            upk2(p01, a, c); ov.x = a + bo; ov.y = c + bo;                  \
            upk2(p23, a, c); ov.z = a + bo; ov.w = c + bo;                  \
            *reinterpret_cast<float4*>(outp + (G) * 4) = ov;                \
        }                                                                   \
    } while (0)

    const int NG = RNN_T / 4;  // 128 (even)
    for (int g = 0; g < NG; g += 2) {
        LOAD_GROUP(bufB, g + 1);
        if (g + 2 < NG) {
            const float4* pf = &xq[(size_t)(g + 2) * 7];
            asm volatile("prefetch.global.L2 [%0];" :: "l"(pf));
        }
        PROCESS_GROUP(bufA, g);
        if (g + 2 < NG) LOAD_GROUP(bufA, g + 2);
        if (g + 3 < NG) {
            const float4* pf = &xq[(size_t)(g + 3) * 7];
            asm volatile("prefetch.global.L2 [%0];" :: "l"(pf));
        }
        PROCESS_GROUP(bufB, g + 1);
    }

    // hidden [1, B, H]
    if (hidden) {
        float* hp = hidden + (size_t)b * RNN_H;
        hp[r0] = t0;
        if (r1 < RNN_H) hp[r1] = t1;
    }
#undef LOAD_GROUP
#undef PROCESS_GROUP
}

extern "C" void kernel_launch(void* const* d_in, const int* in_sizes, int n_in,
                              void* d_out, int out_size) {
    const float* x    = (const float*)d_in[0];
    const float* W_ih = (const float*)d_in[1];
    const float* W_hh = (const float*)d_in[2];
    const float* b_ih = (const float*)d_in[3];
    const float* b_hh = (const float*)d_in[4];
    const float* W_fc = (const float*)d_in[5];
    const float* b_fc = (const float*)d_in[6];

    float* out = (float*)d_out;
    float* hidden = nullptr;
    if (out_size >= RNN_B * RNN_T + RNN_B * RNN_H)
        hidden = out + (size_t)RNN_B * RNN_T;

    // 32768 threads in 128 blocks of 256 -> one block per SM,
    // uniform 2 warps per SMSP on 128 SMs (20 SMs idle by design:
    // uniformity beats raw SM count for a no-rebalance recurrence).
    dim3 grid(128);
    dim3 block(256);
    rnn_fused_kernel<<<grid, block>>>(x, W_ih, W_hh, b_ih, b_hh, W_fc, b_fc,
                                      out, hidden);
}